// round 5
// baseline (speedup 1.0000x reference)
#include <cuda_runtime.h>
#include <cstdint>

#define BATCH 16
#define NPTS  4096
#define NOUT  1024
#define CIN   256
#define COUT  512
#define KNB   16
#define XOUT_ELEMS (BATCH * NOUT * COUT)   // 8388608
#define FPS_THREADS 512

// Scratch: device globals (no allocation allowed anywhere).
__device__ float g_h[(size_t)BATCH * NPTS * COUT];   // 128 MB: post-MLP features
__device__ int   g_fid[BATCH * NOUT];                // flat FPS indices into B*N

// ---------------- packed f32x2 helpers (bit-exact per-lane .rn) ----------------
static __device__ __forceinline__ unsigned long long pk2(float a, float b) {
    unsigned long long r;
    asm("mov.b64 %0,{%1,%2};" : "=l"(r) : "f"(a), "f"(b));
    return r;
}
static __device__ __forceinline__ void upk2(unsigned long long v, float& a, float& b) {
    asm("mov.b64 {%0,%1},%2;" : "=f"(a), "=f"(b) : "l"(v));
}
static __device__ __forceinline__ unsigned long long addx2(unsigned long long a, unsigned long long b) {
    unsigned long long r;
    asm("add.rn.f32x2 %0,%1,%2;" : "=l"(r) : "l"(a), "l"(b));
    return r;
}
static __device__ __forceinline__ unsigned long long mulx2(unsigned long long a, unsigned long long b) {
    unsigned long long r;
    asm("mul.rn.f32x2 %0,%1,%2;" : "=l"(r) : "l"(a), "l"(b));
    return r;
}
static __device__ __forceinline__ uint32_t f2tf32(float f) {
    uint32_t r;
    asm("cvt.rna.tf32.f32 %0,%1;" : "=r"(r) : "f"(f));
    return r;
}
static __device__ __forceinline__ void mma_tf32(float* c, const uint32_t* a, const uint32_t* b) {
    asm volatile(
        "mma.sync.aligned.m16n8k8.row.col.f32.tf32.tf32.f32 "
        "{%0,%1,%2,%3},{%4,%5,%6,%7},{%8,%9},{%0,%1,%2,%3};"
        : "+f"(c[0]), "+f"(c[1]), "+f"(c[2]), "+f"(c[3])
        : "r"(a[0]), "r"(a[1]), "r"(a[2]), "r"(a[3]), "r"(b[0]), "r"(b[1]));
}

// ---------------- FPS: one CTA (512 threads) per batch ----------------
// Mirrors reference fp32 arithmetic: dist = ((dx*dx + dy*dy) + dz*dz), all .rn,
// NO fma contraction. Running min + first-occurrence argmax.
static __device__ void fps_block(const float* __restrict__ p, float* __restrict__ out, char* smem)
{
    const int b = blockIdx.x;
    float* s_p   = (float*)smem;                // 4096*3 floats, interleaved xyz
    int*   s_fid = (int*)(s_p + 3 * NPTS);      // 1024
    float* s_rv  = (float*)(s_fid + NOUT);      // 16
    int*   s_ri  = (int*)(s_rv + 16);           // 16
    int*   s_win = s_ri + 16;                   // 1

    const float* pb = p + (size_t)b * NPTS * 3;
    const int t = threadIdx.x;
    for (int i = t; i < 3 * NPTS; i += FPS_THREADS) s_p[i] = pb[i];
    if (t == 0) s_fid[0] = 0;
    __syncthreads();

    const int base = t * 8;
    unsigned long long Px[4], Py[4], Pz[4];
    float d[8];
#pragma unroll
    for (int q = 0; q < 4; ++q) {
        const int j0 = base + 2 * q;
        Px[q] = pk2(s_p[3 * j0 + 0], s_p[3 * j0 + 3]);
        Py[q] = pk2(s_p[3 * j0 + 1], s_p[3 * j0 + 4]);
        Pz[q] = pk2(s_p[3 * j0 + 2], s_p[3 * j0 + 5]);
    }
#pragma unroll
    for (int j = 0; j < 8; ++j) d[j] = __int_as_float(0x7f800000);  // +inf

    float cx = s_p[0], cy = s_p[1], cz = s_p[2];  // center = point 0
    const int lane = t & 31, warp = t >> 5;

    for (int it = 1; it < NOUT; ++it) {
        const unsigned long long nx = pk2(-cx, -cx);
        const unsigned long long ny = pk2(-cy, -cy);
        const unsigned long long nz = pk2(-cz, -cz);
        float best = -1.0f;
        int bi = base;
#pragma unroll
        for (int q = 0; q < 4; ++q) {
            unsigned long long dx = addx2(Px[q], nx);
            unsigned long long dy = addx2(Py[q], ny);
            unsigned long long dz = addx2(Pz[q], nz);
            unsigned long long s =
                addx2(addx2(mulx2(dx, dx), mulx2(dy, dy)), mulx2(dz, dz));
            float s0, s1;
            upk2(s, s0, s1);
            float d0 = fminf(d[2 * q], s0);
            float d1 = fminf(d[2 * q + 1], s1);
            d[2 * q] = d0;
            d[2 * q + 1] = d1;
            if (d0 > best) { best = d0; bi = base + 2 * q; }
            if (d1 > best) { best = d1; bi = base + 2 * q + 1; }
        }
        // warp argmax: d >= 0 so float bits are monotonic as u32
        const unsigned bb = __float_as_uint(best);
        const unsigned wm = __reduce_max_sync(0xffffffffu, bb);
        const unsigned msk = __ballot_sync(0xffffffffu, bb == wm);
        const int src = __ffs(msk) - 1;              // lowest lane = lowest point idx
        const int wbi = __shfl_sync(0xffffffffu, bi, src);
        if (lane == 0) { s_rv[warp] = __uint_as_float(wm); s_ri[warp] = wbi; }
        __syncthreads();
        if (warp == 0) {
            const unsigned v = (lane < 16) ? __float_as_uint(s_rv[lane]) : 0u;
            const unsigned m2 = __reduce_max_sync(0xffffffffu, v);
            const unsigned e2 = __ballot_sync(0xffffffffu, (v == m2) && (lane < 16));
            const int s2 = __ffs(e2) - 1;            // lowest warp = lowest point idx
            if (lane == 0) {
                const int win = s_ri[s2];
                s_win[0] = win;
                s_fid[it] = win;
            }
        }
        __syncthreads();
        const int w = s_win[0];
        cx = s_p[3 * w];
        cy = s_p[3 * w + 1];
        cz = s_p[3 * w + 2];
    }

    // outputs: flat fid for gather kernel + p_out (after x_out region)
    for (int i = t; i < NOUT; i += FPS_THREADS) {
        const int li = s_fid[i];
        g_fid[b * NOUT + i] = b * NPTS + li;
        float* po = out + (size_t)XOUT_ELEMS + (size_t)(b * NOUT + i) * 3;
        po[0] = s_p[3 * li];
        po[1] = s_p[3 * li + 1];
        po[2] = s_p[3 * li + 2];
    }
}

// ---------------- GEMM: h = ReLU(BN(x @ W^T + b)), tf32 mma.sync ----------------
// CTA tile 128x128, 512 threads = 16 warps (4x4), warp tile 32x32, K-chunk 32.
static __device__ void gemm_block(const float* __restrict__ x, const float* __restrict__ Wm,
                                  const float* __restrict__ bias, const float* __restrict__ gamma,
                                  const float* __restrict__ beta, const float* __restrict__ mean,
                                  const float* __restrict__ var, int g, char* smem)
{
    float* As   = (float*)smem;        // 128 x 36 (padded)
    float* Bs   = As + 128 * 36;       // 128 x 36
    float* s_sc = Bs + 128 * 36;       // 128
    float* s_sh = s_sc + 128;          // 128

    const int m0 = (g >> 2) * 128;     // 512 M-tiles
    const int n0 = (g & 3) * 128;      // 4 N-tiles
    const int t = threadIdx.x, lane = t & 31, warp = t >> 5;
    const int wm = warp >> 2, wn = warp & 3;
    const int grp = lane >> 2, tg = lane & 3;

    if (t < 128) {
        const int c = n0 + t;
        const float sc = gamma[c] * rsqrtf(var[c] + 1e-5f);
        s_sc[t] = sc;
        s_sh[t] = (bias[c] - mean[c]) * sc + beta[c];
    }

    float acc[2][4][4];
#pragma unroll
    for (int mt = 0; mt < 2; ++mt)
#pragma unroll
        for (int nt = 0; nt < 4; ++nt)
#pragma unroll
            for (int j = 0; j < 4; ++j) acc[mt][nt][j] = 0.0f;

    for (int kc = 0; kc < CIN; kc += 32) {
#pragma unroll
        for (int r = 0; r < 2; ++r) {
            const int fi = t + r * 512;
            const int row = fi >> 3, c4 = (fi & 7) * 4;
            const float4 va = *(const float4*)(x + (size_t)(m0 + row) * CIN + kc + c4);
            *(float4*)(As + row * 36 + c4) = va;
            const float4 vb = *(const float4*)(Wm + (size_t)(n0 + row) * CIN + kc + c4);
            *(float4*)(Bs + row * 36 + c4) = vb;
        }
        __syncthreads();
#pragma unroll
        for (int ks = 0; ks < 4; ++ks) {
            const int kb = ks * 8;
            uint32_t a[2][4], bf[4][2];
#pragma unroll
            for (int mt = 0; mt < 2; ++mt) {
                const float* ap = As + (wm * 32 + mt * 16 + grp) * 36 + kb + tg;
                a[mt][0] = f2tf32(ap[0]);
                a[mt][1] = f2tf32(ap[8 * 36]);
                a[mt][2] = f2tf32(ap[4]);
                a[mt][3] = f2tf32(ap[8 * 36 + 4]);
            }
#pragma unroll
            for (int nt = 0; nt < 4; ++nt) {
                const float* bp = Bs + (wn * 32 + nt * 8 + grp) * 36 + kb + tg;
                bf[nt][0] = f2tf32(bp[0]);
                bf[nt][1] = f2tf32(bp[4]);
            }
#pragma unroll
            for (int mt = 0; mt < 2; ++mt)
#pragma unroll
                for (int nt = 0; nt < 4; ++nt) mma_tf32(acc[mt][nt], a[mt], bf[nt]);
        }
        __syncthreads();
    }

    // epilogue: BN(eval) + ReLU, write to g_h
#pragma unroll
    for (int mt = 0; mt < 2; ++mt) {
#pragma unroll
        for (int nt = 0; nt < 4; ++nt) {
#pragma unroll
            for (int j = 0; j < 4; ++j) {
                const int row = m0 + wm * 32 + mt * 16 + grp + (j >> 1) * 8;
                const int lc = wn * 32 + nt * 8 + tg * 2 + (j & 1);
                float v = acc[mt][nt][j] * s_sc[lc] + s_sh[lc];
                v = fmaxf(v, 0.0f);
                g_h[(size_t)row * COUT + n0 + lc] = v;
            }
        }
    }
}

// ---------------- fused kernel: FPS blocks 0..15 (wave 1) + GEMM blocks ----------------
__global__ __launch_bounds__(FPS_THREADS)
void fused_kernel(const float* __restrict__ x, const float* __restrict__ p,
                  const float* __restrict__ Wm, const float* __restrict__ bias,
                  const float* __restrict__ gamma, const float* __restrict__ beta,
                  const float* __restrict__ mean, const float* __restrict__ var,
                  float* __restrict__ out)
{
    extern __shared__ char smem[];
    if (blockIdx.x < 16)
        fps_block(p, out, smem);
    else
        gemm_block(x, Wm, bias, gamma, beta, mean, var, (int)blockIdx.x - 16, smem);
}

// ---------------- gather + maxpool over K neighbors ----------------
// sid_euc dtype is int32 in practice (JAX default jax_enable_x64=False makes
// astype(int64) a no-op). Deterministic sniff: if the buffer were really
// int64 little-endian, every odd 32-bit word is 0 (indices < 65536). For a
// genuine random int32 buffer, 4 consecutive odd words all zero has p~1e-19.
__global__ __launch_bounds__(128)
void gather_kernel(const int* __restrict__ sid32, float* __restrict__ out)
{
    __shared__ int s_idx[KNB];
    const int r = blockIdx.x;     // output row in [0, B*n)
    const int t = threadIdx.x;    // channel group: float4 at col t*4
    if (t < KNB) {
        const bool is64 = (sid32[1] == 0) && (sid32[3] == 0) &&
                          (sid32[5] == 0) && (sid32[7] == 0);
        const int fidf = g_fid[r];
        s_idx[t] = is64 ? sid32[((size_t)fidf * KNB + t) * 2]
                        : sid32[(size_t)fidf * KNB + t];
    }
    __syncthreads();
    float4 m = *(const float4*)(g_h + (size_t)s_idx[0] * COUT + t * 4);
#pragma unroll
    for (int k = 1; k < KNB; ++k) {
        const float4 v = *(const float4*)(g_h + (size_t)s_idx[k] * COUT + t * 4);
        m.x = fmaxf(m.x, v.x);
        m.y = fmaxf(m.y, v.y);
        m.z = fmaxf(m.z, v.z);
        m.w = fmaxf(m.w, v.w);
    }
    *(float4*)(out + (size_t)r * COUT + t * 4) = m;
}

// ---------------- launch ----------------
#define FUSED_SMEM 53504  // max(FPS: 53380, GEMM: 37888), padded

extern "C" void kernel_launch(void* const* d_in, const int* in_sizes, int n_in,
                              void* d_out, int out_size)
{
    (void)in_sizes; (void)n_in; (void)out_size;
    const float* x      = (const float*)d_in[0];
    const float* p      = (const float*)d_in[1];
    const int*   sid    = (const int*)d_in[2];   // int32 (x64 disabled in JAX)
    // d_in[3] = tid_euc (unused by reference)
    const float* W      = (const float*)d_in[4];
    const float* bias   = (const float*)d_in[5];
    const float* gamma  = (const float*)d_in[6];
    const float* beta   = (const float*)d_in[7];
    const float* mean   = (const float*)d_in[8];
    const float* var    = (const float*)d_in[9];
    float* out = (float*)d_out;

    // Opt-in to >48KB dynamic smem (host-side, idempotent, capture-legal).
    cudaFuncSetAttribute(fused_kernel, cudaFuncAttributeMaxDynamicSharedMemorySize, FUSED_SMEM);

    const int gemm_blocks = (BATCH * NPTS / 128) * (COUT / 128);  // 2048
    fused_kernel<<<16 + gemm_blocks, FPS_THREADS, FUSED_SMEM>>>(
        x, p, W, bias, gamma, beta, mean, var, out);
    gather_kernel<<<BATCH * NOUT, 128>>>(sid, out);
}